// round 5
// baseline (speedup 1.0000x reference)
#include <cuda_runtime.h>
#include <cuda_bf16.h>
#include <mma.h>

using namespace nvcuda;

// Problem constants
#define T_TOK 4096
#define D_MODEL 2048
#define F_FF 8192
#define E_EXP 8

// ---------------------------------------------------------------------------
// Device scratch (no dynamic allocation allowed)
// ---------------------------------------------------------------------------
__device__ int   g_idx[T_TOK];          // selected expert per token
__device__ float g_w[T_TOK];            // router weight per token
__device__ int   g_cnt[E_EXP];          // tokens per expert
__device__ int   g_off[E_EXP + 1];      // exclusive prefix of counts
__device__ int   g_slot[T_TOK];         // slot of token within its expert
__device__ int   g_perm[T_TOK];         // perm[p] = token  (p = off[e]+slot)
__device__ float g_H[(size_t)T_TOK * F_FF];   // 128 MB fp32 hidden scratch

// ---------------------------------------------------------------------------
// Kernel 0: reset counters (graph replays must be deterministic)
// ---------------------------------------------------------------------------
__global__ void init_kernel() {
    if (threadIdx.x < E_EXP) g_cnt[threadIdx.x] = 0;
}

// ---------------------------------------------------------------------------
// Kernel 1: router. One block per token, 128 threads.
// logits[e] = sum_d x[t,d] * Wr[e,d]; softmax -> argmax prob + weight.
// ---------------------------------------------------------------------------
__global__ void router_kernel(const float* __restrict__ x,
                              const float* __restrict__ Wr) {
    const int t   = blockIdx.x;
    const int tid = threadIdx.x;
    __shared__ float red[E_EXP][128];

    const float* xr = x + (size_t)t * D_MODEL;
    float acc[E_EXP];
#pragma unroll
    for (int e = 0; e < E_EXP; e++) acc[e] = 0.f;

    for (int d = tid; d < D_MODEL; d += 128) {
        float xv = xr[d];
#pragma unroll
        for (int e = 0; e < E_EXP; e++)
            acc[e] = fmaf(xv, Wr[(size_t)e * D_MODEL + d], acc[e]);
    }
#pragma unroll
    for (int e = 0; e < E_EXP; e++) red[e][tid] = acc[e];
    __syncthreads();

    for (int s = 64; s > 0; s >>= 1) {
        if (tid < s) {
#pragma unroll
            for (int e = 0; e < E_EXP; e++) red[e][tid] += red[e][tid + s];
        }
        __syncthreads();
    }

    if (tid == 0) {
        float m = red[0][0];
        int   bi = 0;
#pragma unroll
        for (int e = 1; e < E_EXP; e++) {
            float v = red[e][0];
            if (v > m) { m = v; bi = e; }   // strict > keeps first max (jnp.argmax)
        }
        float s = 0.f;
#pragma unroll
        for (int e = 0; e < E_EXP; e++) s += __expf(0.f) * 0.f + expf(red[e][0] - m);
        g_idx[t]  = bi;
        g_w[t]    = 1.0f / s;               // exp(lmax-m)=1 over sum
        g_slot[t] = atomicAdd(&g_cnt[bi], 1);
    }
}

// ---------------------------------------------------------------------------
// Kernel 2: exclusive prefix of counts
// ---------------------------------------------------------------------------
__global__ void offsets_kernel() {
    if (threadIdx.x == 0) {
        int s = 0;
        for (int e = 0; e < E_EXP; e++) { g_off[e] = s; s += g_cnt[e]; }
        g_off[E_EXP] = s;
    }
}

// ---------------------------------------------------------------------------
// Kernel 3: build permutation
// ---------------------------------------------------------------------------
__global__ void perm_kernel() {
    int t = blockIdx.x * 256 + threadIdx.x;
    if (t < T_TOK) g_perm[g_off[g_idx[t]] + g_slot[t]] = t;
}

// ---------------------------------------------------------------------------
// Exact GELU (matches jax.nn.gelu approximate=False)
// ---------------------------------------------------------------------------
__device__ __forceinline__ float gelu_exact(float v) {
    return 0.5f * v * (1.0f + erff(v * 0.70710678118654752440f));
}

// ---------------------------------------------------------------------------
// Grouped GEMM kernels (WMMA TF32, 128x128x16 block tile, 8 warps of 64x32)
// grid: (N/128, T/128, E). Blocks with mt*128 >= cnt[e] exit.
// ---------------------------------------------------------------------------
#define BM 128
#define BN 128
#define BK 16

__global__ __launch_bounds__(256, 2)
void gemm1_kernel(const float* __restrict__ x,
                  const float* __restrict__ W1) {
    const int e  = blockIdx.z;
    const int mt = blockIdx.y;
    const int nt = blockIdx.x;
    const int cnt = g_cnt[e];
    const int off = g_off[e];
    if (mt * BM >= cnt) return;

    __shared__ float As[BM][BK];
    __shared__ float Bs[BK][BN + 8];
    __shared__ float stage[8][16 * 16];

    const int tid   = threadIdx.x;
    const int warp  = tid >> 5;
    const int lane  = tid & 31;
    const int warpM = warp & 1;     // 0..1 -> 64 rows each
    const int warpN = warp >> 1;    // 0..3 -> 32 cols each

    // --- precompute A sources (gather via perm), guarded ---
    const int rA   = tid >> 2;             // 0..63 (+64 for second)
    const int colA = (tid & 3) * 4;
    const float* aSrc[2];
#pragma unroll
    for (int i = 0; i < 2; i++) {
        int grow = mt * BM + rA + i * 64;
        if (grow < cnt) {
            int tok = g_perm[off + grow];
            aSrc[i] = x + (size_t)tok * D_MODEL + colA;
        } else {
            aSrc[i] = nullptr;
        }
    }
    // --- B source ---
    const int rB   = tid >> 5;             // 0..7 (+8 for second)
    const int colB = (tid & 31) * 4;
    const float* bBase = W1 + (size_t)e * D_MODEL * F_FF
                            + (size_t)nt * BN + colB;

    wmma::fragment<wmma::accumulator, 16, 16, 8, float> c[4][2];
#pragma unroll
    for (int i = 0; i < 4; i++)
#pragma unroll
        for (int j = 0; j < 2; j++) wmma::fill_fragment(c[i][j], 0.0f);

#pragma unroll 1
    for (int k0 = 0; k0 < D_MODEL; k0 += BK) {
        // load A tile
#pragma unroll
        for (int i = 0; i < 2; i++) {
            float4 v = make_float4(0.f, 0.f, 0.f, 0.f);
            if (aSrc[i]) v = *(const float4*)(aSrc[i] + k0);
            *(float4*)&As[rA + i * 64][colA] = v;
        }
        // load B tile
#pragma unroll
        for (int i = 0; i < 2; i++) {
            float4 v = *(const float4*)(bBase + (size_t)(k0 + rB + i * 8) * F_FF);
            *(float4*)&Bs[rB + i * 8][colB] = v;
        }
        __syncthreads();

#pragma unroll
        for (int ks = 0; ks < 2; ks++) {
            wmma::fragment<wmma::matrix_a, 16, 16, 8, wmma::precision::tf32, wmma::row_major> a[4];
            wmma::fragment<wmma::matrix_b, 16, 16, 8, wmma::precision::tf32, wmma::row_major> b[2];
#pragma unroll
            for (int i = 0; i < 4; i++) {
                wmma::load_matrix_sync(a[i], &As[warpM * 64 + i * 16][ks * 8], BK);
#pragma unroll
                for (int q = 0; q < a[i].num_elements; q++)
                    a[i].x[q] = wmma::__float_to_tf32(a[i].x[q]);
            }
#pragma unroll
            for (int j = 0; j < 2; j++) {
                wmma::load_matrix_sync(b[j], &Bs[ks * 8][warpN * 32 + j * 16], BN + 8);
#pragma unroll
                for (int q = 0; q < b[j].num_elements; q++)
                    b[j].x[q] = wmma::__float_to_tf32(b[j].x[q]);
            }
#pragma unroll
            for (int i = 0; i < 4; i++)
#pragma unroll
                for (int j = 0; j < 2; j++)
                    wmma::mma_sync(c[i][j], a[i], b[j], c[i][j]);
        }
        __syncthreads();
    }

    // --- epilogue: GELU, guarded store to compact H ---
    float* stg = stage[warp];
#pragma unroll
    for (int i = 0; i < 4; i++) {
#pragma unroll
        for (int j = 0; j < 2; j++) {
#pragma unroll
            for (int q = 0; q < c[i][j].num_elements; q++)
                c[i][j].x[q] = gelu_exact(c[i][j].x[q]);
            wmma::store_matrix_sync(stg, c[i][j], 16, wmma::mem_row_major);
            __syncwarp();
            const int r0 = mt * BM + warpM * 64 + i * 16;
            const int c0 = nt * BN + warpN * 32 + j * 16;
#pragma unroll
            for (int k = 0; k < 8; k++) {
                int idx = k * 32 + lane;
                int rr = idx >> 4, cc = idx & 15;
                int gr = r0 + rr;
                if (gr < cnt)
                    g_H[(size_t)(off + gr) * F_FF + c0 + cc] = stg[idx];
            }
            __syncwarp();
        }
    }
}

__global__ __launch_bounds__(256, 2)
void gemm2_kernel(const float* __restrict__ W2,
                  float* __restrict__ out) {
    const int e  = blockIdx.z;
    const int mt = blockIdx.y;
    const int nt = blockIdx.x;
    const int cnt = g_cnt[e];
    const int off = g_off[e];
    if (mt * BM >= cnt) return;

    __shared__ float As[BM][BK];
    __shared__ float Bs[BK][BN + 8];
    __shared__ float stage[8][16 * 16];

    const int tid   = threadIdx.x;
    const int warp  = tid >> 5;
    const int lane  = tid & 31;
    const int warpM = warp & 1;
    const int warpN = warp >> 1;

    const int rA   = tid >> 2;
    const int colA = (tid & 3) * 4;
    const float* aSrc[2];
#pragma unroll
    for (int i = 0; i < 2; i++) {
        int grow = mt * BM + rA + i * 64;
        aSrc[i] = (grow < cnt) ? (g_H + (size_t)(off + grow) * F_FF + colA)
                               : nullptr;
    }
    const int rB   = tid >> 5;
    const int colB = (tid & 31) * 4;
    const float* bBase = W2 + (size_t)e * F_FF * D_MODEL
                            + (size_t)nt * BN + colB;

    wmma::fragment<wmma::accumulator, 16, 16, 8, float> c[4][2];
#pragma unroll
    for (int i = 0; i < 4; i++)
#pragma unroll
        for (int j = 0; j < 2; j++) wmma::fill_fragment(c[i][j], 0.0f);

#pragma unroll 1
    for (int k0 = 0; k0 < F_FF; k0 += BK) {
#pragma unroll
        for (int i = 0; i < 2; i++) {
            float4 v = make_float4(0.f, 0.f, 0.f, 0.f);
            if (aSrc[i]) v = *(const float4*)(aSrc[i] + k0);
            *(float4*)&As[rA + i * 64][colA] = v;
        }
#pragma unroll
        for (int i = 0; i < 2; i++) {
            float4 v = *(const float4*)(bBase + (size_t)(k0 + rB + i * 8) * D_MODEL);
            *(float4*)&Bs[rB + i * 8][colB] = v;
        }
        __syncthreads();

#pragma unroll
        for (int ks = 0; ks < 2; ks++) {
            wmma::fragment<wmma::matrix_a, 16, 16, 8, wmma::precision::tf32, wmma::row_major> a[4];
            wmma::fragment<wmma::matrix_b, 16, 16, 8, wmma::precision::tf32, wmma::row_major> b[2];
#pragma unroll
            for (int i = 0; i < 4; i++) {
                wmma::load_matrix_sync(a[i], &As[warpM * 64 + i * 16][ks * 8], BK);
#pragma unroll
                for (int q = 0; q < a[i].num_elements; q++)
                    a[i].x[q] = wmma::__float_to_tf32(a[i].x[q]);
            }
#pragma unroll
            for (int j = 0; j < 2; j++) {
                wmma::load_matrix_sync(b[j], &Bs[ks * 8][warpN * 32 + j * 16], BN + 8);
#pragma unroll
                for (int q = 0; q < b[j].num_elements; q++)
                    b[j].x[q] = wmma::__float_to_tf32(b[j].x[q]);
            }
#pragma unroll
            for (int i = 0; i < 4; i++)
#pragma unroll
                for (int j = 0; j < 2; j++)
                    wmma::mma_sync(c[i][j], a[i], b[j], c[i][j]);
        }
        __syncthreads();
    }

    // --- epilogue: scale by router weight, scatter to out[token] ---
    float* stg = stage[warp];
#pragma unroll
    for (int i = 0; i < 4; i++) {
#pragma unroll
        for (int j = 0; j < 2; j++) {
            wmma::store_matrix_sync(stg, c[i][j], 16, wmma::mem_row_major);
            __syncwarp();
            const int r0 = mt * BM + warpM * 64 + i * 16;
            const int c0 = nt * BN + warpN * 32 + j * 16;
#pragma unroll
            for (int k = 0; k < 8; k++) {
                int idx = k * 32 + lane;
                int rr = idx >> 4, cc = idx & 15;
                int gr = r0 + rr;
                if (gr < cnt) {
                    int tok = g_perm[off + gr];
                    out[(size_t)tok * D_MODEL + c0 + cc] = stg[idx] * g_w[tok];
                }
            }
            __syncwarp();
        }
    }
}

// ---------------------------------------------------------------------------
// Launch
// ---------------------------------------------------------------------------
extern "C" void kernel_launch(void* const* d_in, const int* in_sizes, int n_in,
                              void* d_out, int out_size) {
    const float* x  = (const float*)d_in[0];   // [T, D]
    const float* Wr = (const float*)d_in[1];   // [E, D]
    const float* W1 = (const float*)d_in[2];   // [E, D, F]
    const float* W2 = (const float*)d_in[3];   // [E, F, D]
    float* out = (float*)d_out;                // [T, D]

    init_kernel<<<1, 32>>>();
    router_kernel<<<T_TOK, 128>>>(x, Wr);
    offsets_kernel<<<1, 32>>>();
    perm_kernel<<<T_TOK / 256, 256>>>();

    dim3 g1(F_FF / BN, T_TOK / BM, E_EXP);     // (64, 32, 8)
    gemm1_kernel<<<g1, 256>>>(x, W1);

    dim3 g2(D_MODEL / BN, T_TOK / BM, E_EXP);  // (16, 32, 8)
    gemm2_kernel<<<g2, 256>>>(W2, out);
}

// round 7
// speedup vs baseline: 1.0542x; 1.0542x over previous
#include <cuda_runtime.h>
#include <cuda_bf16.h>
#include <mma.h>
#include <cstdint>

using namespace nvcuda;

// Problem constants
#define T_TOK 4096
#define D_MODEL 2048
#define F_FF 8192
#define E_EXP 8

// GEMM tiling
#define BM 256
#define BN 128
#define BK 32
#define NTHREADS 512
#define LDA_S 40              // padded A row (floats): 160B, 32B-aligned
#define LDB_S 136             // padded B row (floats): 544B, 32B-aligned
#define ABUF (BM * LDA_S)     // 10240 floats
#define BBUF (BK * LDB_S)     // 4352 floats
#define BUF_FLOATS (ABUF + BBUF)
#define SMEM_BYTES (2 * BUF_FLOATS * 4)   // 116736 B

// ---------------------------------------------------------------------------
// Device scratch (no dynamic allocation allowed)
// ---------------------------------------------------------------------------
__device__ int   g_idx[T_TOK];
__device__ float g_w[T_TOK];
__device__ int   g_cnt[E_EXP];
__device__ int   g_off[E_EXP + 1];
__device__ int   g_slot[T_TOK];
__device__ int   g_perm[T_TOK];
__device__ float g_H[(size_t)T_TOK * F_FF];   // 128 MB fp32 hidden scratch

// ---------------------------------------------------------------------------
// cp.async helpers
// ---------------------------------------------------------------------------
__device__ __forceinline__ void cp_async16(uint32_t dst, const void* src) {
    asm volatile("cp.async.cg.shared.global [%0], [%1], 16;\n" :: "r"(dst), "l"(src));
}
__device__ __forceinline__ void cp_commit() {
    asm volatile("cp.async.commit_group;\n");
}
template <int N>
__device__ __forceinline__ void cp_wait() {
    asm volatile("cp.async.wait_group %0;\n" :: "n"(N));
}

// ---------------------------------------------------------------------------
// Kernel 0: reset counters (graph replays must be deterministic)
// ---------------------------------------------------------------------------
__global__ void init_kernel() {
    if (threadIdx.x < E_EXP) g_cnt[threadIdx.x] = 0;
}

// ---------------------------------------------------------------------------
// Kernel 1: router. One block per token, 128 threads.
// ---------------------------------------------------------------------------
__global__ void router_kernel(const float* __restrict__ x,
                              const float* __restrict__ Wr) {
    const int t   = blockIdx.x;
    const int tid = threadIdx.x;
    __shared__ float red[E_EXP][128];

    const float* xr = x + (size_t)t * D_MODEL;
    float acc[E_EXP];
#pragma unroll
    for (int e = 0; e < E_EXP; e++) acc[e] = 0.f;

    for (int d = tid; d < D_MODEL; d += 128) {
        float xv = xr[d];
#pragma unroll
        for (int e = 0; e < E_EXP; e++)
            acc[e] = fmaf(xv, Wr[(size_t)e * D_MODEL + d], acc[e]);
    }
#pragma unroll
    for (int e = 0; e < E_EXP; e++) red[e][tid] = acc[e];
    __syncthreads();

    for (int s = 64; s > 0; s >>= 1) {
        if (tid < s) {
#pragma unroll
            for (int e = 0; e < E_EXP; e++) red[e][tid] += red[e][tid + s];
        }
        __syncthreads();
    }

    if (tid == 0) {
        float m = red[0][0];
        int   bi = 0;
#pragma unroll
        for (int e = 1; e < E_EXP; e++) {
            float v = red[e][0];
            if (v > m) { m = v; bi = e; }   // strict > keeps first max (jnp.argmax)
        }
        float s = 0.f;
#pragma unroll
        for (int e = 0; e < E_EXP; e++) s += expf(red[e][0] - m);
        g_idx[t]  = bi;
        g_w[t]    = 1.0f / s;               // exp(lmax-m)=1 over sum
        g_slot[t] = atomicAdd(&g_cnt[bi], 1);
    }
}

// ---------------------------------------------------------------------------
// Kernel 2: exclusive prefix of counts
// ---------------------------------------------------------------------------
__global__ void offsets_kernel() {
    if (threadIdx.x == 0) {
        int s = 0;
        for (int e = 0; e < E_EXP; e++) { g_off[e] = s; s += g_cnt[e]; }
        g_off[E_EXP] = s;
    }
}

// ---------------------------------------------------------------------------
// Kernel 3: build permutation
// ---------------------------------------------------------------------------
__global__ void perm_kernel() {
    int t = blockIdx.x * 256 + threadIdx.x;
    if (t < T_TOK) g_perm[g_off[g_idx[t]] + g_slot[t]] = t;
}

// ---------------------------------------------------------------------------
// Exact GELU (matches jax.nn.gelu approximate=False)
// ---------------------------------------------------------------------------
__device__ __forceinline__ float gelu_exact(float v) {
    return 0.5f * v * (1.0f + erff(v * 0.70710678118654752440f));
}

// ---------------------------------------------------------------------------
// GEMM1: H[off+m, n] = gelu( sum_k X[perm[off+m], k] * W1[e][k][n] )
// 256x128x32 tiles, cp.async double-buffered, 512 threads (16 warps, 64x32).
// ---------------------------------------------------------------------------
__global__ __launch_bounds__(NTHREADS)
void gemm1_kernel(const float* __restrict__ x,
                  const float* __restrict__ W1) {
    const int e  = blockIdx.z;
    const int mt = blockIdx.y;
    const int nt = blockIdx.x;
    const int cnt = g_cnt[e];
    const int off = g_off[e];
    if (mt * BM >= cnt) return;

    extern __shared__ float smem[];
    const int tid  = threadIdx.x;
    const int warp = tid >> 5;
    const int lane = tid & 31;
    const int warpM = warp & 3;    // 0..3 -> 64 rows each
    const int warpN = warp >> 2;   // 0..3 -> 32 cols each

    // --- A gather sources: 4 rows per thread, clamped (OOB rows never stored)
    const int rA = tid >> 3;            // 0..63
    const int cA = (tid & 7) * 4;       // 0..28
    const float* aptr[4];
#pragma unroll
    for (int i = 0; i < 4; i++) {
        int grow = mt * BM + rA + 64 * i;
        int r = grow < cnt ? grow : cnt - 1;
        int tok = g_perm[off + r];
        aptr[i] = x + (size_t)tok * D_MODEL + cA;
    }
    // --- B sources: 2 float4 per thread
    const float* wbase = W1 + (size_t)e * D_MODEL * F_FF + (size_t)nt * BN;
    const float* bptr[2];
    int kkB[2], cB[2];
#pragma unroll
    for (int i = 0; i < 2; i++) {
        int q = tid + NTHREADS * i;     // 0..1023
        kkB[i] = q >> 5;                // 0..31
        cB[i]  = (q & 31) * 4;          // 0..124
        bptr[i] = wbase + (size_t)kkB[i] * F_FF + cB[i];
    }
    // --- smem destinations (buffer 0; buffer 1 = +BUF_FLOATS*4 bytes)
    uint32_t dA[4], dB[2];
#pragma unroll
    for (int i = 0; i < 4; i++)
        dA[i] = (uint32_t)__cvta_generic_to_shared(&smem[(rA + 64 * i) * LDA_S + cA]);
#pragma unroll
    for (int i = 0; i < 2; i++)
        dB[i] = (uint32_t)__cvta_generic_to_shared(&smem[ABUF + kkB[i] * LDB_S + cB[i]]);

    auto prefetch = [&](int b, int k0) {
        uint32_t add = (uint32_t)b * (uint32_t)(BUF_FLOATS * 4);
#pragma unroll
        for (int i = 0; i < 4; i++) cp_async16(dA[i] + add, aptr[i] + k0);
#pragma unroll
        for (int i = 0; i < 2; i++) cp_async16(dB[i] + add, bptr[i] + (size_t)k0 * F_FF);
    };

    wmma::fragment<wmma::accumulator, 16, 16, 8, float> c[4][2];
#pragma unroll
    for (int i = 0; i < 4; i++)
#pragma unroll
        for (int j = 0; j < 2; j++) wmma::fill_fragment(c[i][j], 0.0f);

    const int NK = D_MODEL / BK;   // 64
    prefetch(0, 0);
    cp_commit();

#pragma unroll 1
    for (int kt = 0; kt < NK; kt++) {
        const int cur = kt & 1;
        if (kt + 1 < NK) prefetch(cur ^ 1, (kt + 1) * BK);
        cp_commit();
        cp_wait<1>();
        __syncthreads();

        const float* As = smem + cur * BUF_FLOATS;
        const float* Bs = As + ABUF;
#pragma unroll
        for (int ks = 0; ks < BK / 8; ks++) {
            wmma::fragment<wmma::matrix_a, 16, 16, 8, wmma::precision::tf32, wmma::row_major> a[4];
            wmma::fragment<wmma::matrix_b, 16, 16, 8, wmma::precision::tf32, wmma::row_major> b[2];
#pragma unroll
            for (int i = 0; i < 4; i++) {
                wmma::load_matrix_sync(a[i], &As[(warpM * 64 + i * 16) * LDA_S + ks * 8], LDA_S);
#pragma unroll
                for (int q = 0; q < a[i].num_elements; q++)
                    a[i].x[q] = wmma::__float_to_tf32(a[i].x[q]);
            }
#pragma unroll
            for (int j = 0; j < 2; j++) {
                wmma::load_matrix_sync(b[j], &Bs[(ks * 8) * LDB_S + warpN * 32 + j * 16], LDB_S);
#pragma unroll
                for (int q = 0; q < b[j].num_elements; q++)
                    b[j].x[q] = wmma::__float_to_tf32(b[j].x[q]);
            }
#pragma unroll
            for (int i = 0; i < 4; i++)
#pragma unroll
                for (int j = 0; j < 2; j++)
                    wmma::mma_sync(c[i][j], a[i], b[j], c[i][j]);
        }
        __syncthreads();
    }

    // --- epilogue: GELU, guarded store to compact H (stage overlays k-loop smem)
    float* stg = smem + (warp << 8);   // 256 floats per warp
#pragma unroll
    for (int i = 0; i < 4; i++) {
#pragma unroll
        for (int j = 0; j < 2; j++) {
#pragma unroll
            for (int q = 0; q < c[i][j].num_elements; q++)
                c[i][j].x[q] = gelu_exact(c[i][j].x[q]);
            wmma::store_matrix_sync(stg, c[i][j], 16, wmma::mem_row_major);
            __syncwarp();
            const int r0 = mt * BM + warpM * 64 + i * 16;
            const int c0 = nt * BN + warpN * 32 + j * 16;
#pragma unroll
            for (int k = 0; k < 8; k++) {
                int idx = k * 32 + lane;
                int rr = idx >> 4, cc = idx & 15;
                int gr = r0 + rr;
                if (gr < cnt)
                    g_H[(size_t)(off + gr) * F_FF + c0 + cc] = stg[idx];
            }
            __syncwarp();
        }
    }
}

// ---------------------------------------------------------------------------
// GEMM2: out[tok, n] = w[tok] * sum_k H[off+m, k] * W2[e][k][n]
// ---------------------------------------------------------------------------
__global__ __launch_bounds__(NTHREADS)
void gemm2_kernel(const float* __restrict__ W2,
                  float* __restrict__ out) {
    const int e  = blockIdx.z;
    const int mt = blockIdx.y;
    const int nt = blockIdx.x;
    const int cnt = g_cnt[e];
    const int off = g_off[e];
    if (mt * BM >= cnt) return;

    extern __shared__ float smem[];
    const int tid  = threadIdx.x;
    const int warp = tid >> 5;
    const int lane = tid & 31;
    const int warpM = warp & 3;
    const int warpN = warp >> 2;

    const int rA = tid >> 3;
    const int cA = (tid & 7) * 4;
    const float* aptr[4];
#pragma unroll
    for (int i = 0; i < 4; i++) {
        int grow = mt * BM + rA + 64 * i;
        int r = grow < cnt ? grow : cnt - 1;
        aptr[i] = g_H + (size_t)(off + r) * F_FF + cA;
    }
    const float* wbase = W2 + (size_t)e * F_FF * D_MODEL + (size_t)nt * BN;
    const float* bptr[2];
    int kkB[2], cB[2];
#pragma unroll
    for (int i = 0; i < 2; i++) {
        int q = tid + NTHREADS * i;
        kkB[i] = q >> 5;
        cB[i]  = (q & 31) * 4;
        bptr[i] = wbase + (size_t)kkB[i] * D_MODEL + cB[i];
    }
    uint32_t dA[4], dB[2];
#pragma unroll
    for (int i = 0; i < 4; i++)
        dA[i] = (uint32_t)__cvta_generic_to_shared(&smem[(rA + 64 * i) * LDA_S + cA]);
#pragma unroll
    for (int i = 0; i < 2; i++)
        dB[i] = (uint32_t)__cvta_generic_to_shared(&smem[ABUF + kkB[i] * LDB_S + cB[i]]);

    auto prefetch = [&](int b, int k0) {
        uint32_t add = (uint32_t)b * (uint32_t)(BUF_FLOATS * 4);
#pragma unroll
        for (int i = 0; i < 4; i++) cp_async16(dA[i] + add, aptr[i] + k0);
#pragma unroll
        for (int i = 0; i < 2; i++) cp_async16(dB[i] + add, bptr[i] + (size_t)k0 * D_MODEL);
    };

    wmma::fragment<wmma::accumulator, 16, 16, 8, float> c[4][2];
#pragma unroll
    for (int i = 0; i < 4; i++)
#pragma unroll
        for (int j = 0; j < 2; j++) wmma::fill_fragment(c[i][j], 0.0f);

    const int NK = F_FF / BK;   // 256
    prefetch(0, 0);
    cp_commit();

#pragma unroll 1
    for (int kt = 0; kt < NK; kt++) {
        const int cur = kt & 1;
        if (kt + 1 < NK) prefetch(cur ^ 1, (kt + 1) * BK);
        cp_commit();
        cp_wait<1>();
        __syncthreads();

        const float* As = smem + cur * BUF_FLOATS;
        const float* Bs = As + ABUF;
#pragma unroll
        for (int ks = 0; ks < BK / 8; ks++) {
            wmma::fragment<wmma::matrix_a, 16, 16, 8, wmma::precision::tf32, wmma::row_major> a[4];
            wmma::fragment<wmma::matrix_b, 16, 16, 8, wmma::precision::tf32, wmma::row_major> b[2];
#pragma unroll
            for (int i = 0; i < 4; i++) {
                wmma::load_matrix_sync(a[i], &As[(warpM * 64 + i * 16) * LDA_S + ks * 8], LDA_S);
#pragma unroll
                for (int q = 0; q < a[i].num_elements; q++)
                    a[i].x[q] = wmma::__float_to_tf32(a[i].x[q]);
            }
#pragma unroll
            for (int j = 0; j < 2; j++) {
                wmma::load_matrix_sync(b[j], &Bs[(ks * 8) * LDB_S + warpN * 32 + j * 16], LDB_S);
#pragma unroll
                for (int q = 0; q < b[j].num_elements; q++)
                    b[j].x[q] = wmma::__float_to_tf32(b[j].x[q]);
            }
#pragma unroll
            for (int i = 0; i < 4; i++)
#pragma unroll
                for (int j = 0; j < 2; j++)
                    wmma::mma_sync(c[i][j], a[i], b[j], c[i][j]);
        }
        __syncthreads();
    }

    // --- epilogue: scale by router weight, scatter to out[token]
    float* stg = smem + (warp << 8);
#pragma unroll
    for (int i = 0; i < 4; i++) {
#pragma unroll
        for (int j = 0; j < 2; j++) {
            wmma::store_matrix_sync(stg, c[i][j], 16, wmma::mem_row_major);
            __syncwarp();
            const int r0 = mt * BM + warpM * 64 + i * 16;
            const int c0 = nt * BN + warpN * 32 + j * 16;
#pragma unroll
            for (int k = 0; k < 8; k++) {
                int idx = k * 32 + lane;
                int rr = idx >> 4, cc = idx & 15;
                int gr = r0 + rr;
                if (gr < cnt) {
                    int tok = g_perm[off + gr];
                    out[(size_t)tok * D_MODEL + c0 + cc] = stg[idx] * g_w[tok];
                }
            }
            __syncwarp();
        }
    }
}

// ---------------------------------------------------------------------------
// Launch
// ---------------------------------------------------------------------------
extern "C" void kernel_launch(void* const* d_in, const int* in_sizes, int n_in,
                              void* d_out, int out_size) {
    const float* x  = (const float*)d_in[0];   // [T, D]
    const float* Wr = (const float*)d_in[1];   // [E, D]
    const float* W1 = (const float*)d_in[2];   // [E, D, F]
    const float* W2 = (const float*)d_in[3];   // [E, F, D]
    float* out = (float*)d_out;                // [T, D]

    // Opt-in dynamic smem (immediate, non-stream call: graph-capture legal)
    cudaFuncSetAttribute(gemm1_kernel,
                         cudaFuncAttributeMaxDynamicSharedMemorySize, SMEM_BYTES);
    cudaFuncSetAttribute(gemm2_kernel,
                         cudaFuncAttributeMaxDynamicSharedMemorySize, SMEM_BYTES);

    init_kernel<<<1, 32>>>();
    router_kernel<<<T_TOK, 128>>>(x, Wr);
    offsets_kernel<<<1, 32>>>();
    perm_kernel<<<T_TOK / 256, 256>>>();

    dim3 g1(F_FF / BN, T_TOK / BM, E_EXP);     // (64, 16, 8)
    gemm1_kernel<<<g1, NTHREADS, SMEM_BYTES>>>(x, W1);

    dim3 g2(D_MODEL / BN, T_TOK / BM, E_EXP);  // (16, 16, 8)
    gemm2_kernel<<<g2, NTHREADS, SMEM_BYTES>>>(W2, out);
}

// round 13
// speedup vs baseline: 1.4610x; 1.3859x over previous
#include <cuda_runtime.h>
#include <cuda_bf16.h>
#include <cstdint>

// Problem constants
#define T_TOK 4096
#define D_MODEL 2048
#define F_FF 8192
#define E_EXP 8

// GEMM tiling: 128x128 CTA tile, BK=32, 8 warps, warp tile 32x64
#define BM 128
#define BN 128
#define BK 32
#define NTH 256
#define LDA_S 36                 // A smem stride (floats): bank=(4r+c)%32, conflict-free
#define LDB_S 136                // B smem stride (floats): 136%32=8, bank=(8k+n)%32, conflict-free
#define ABUF (BM * LDA_S)        // 4608 floats
#define BBUF (BK * LDB_S)        // 4352 floats
#define BUF_FLOATS (ABUF + BBUF) // 8960
#define SMEM_BYTES (2 * BUF_FLOATS * 4)   // 71680 B

// ---------------------------------------------------------------------------
// Device scratch
// ---------------------------------------------------------------------------
__device__ int   g_idx[T_TOK];
__device__ float g_w[T_TOK];
__device__ int   g_cnt[E_EXP];
__device__ int   g_off[E_EXP + 1];
__device__ int   g_slot[T_TOK];
__device__ int   g_perm[T_TOK];
__device__ float g_H[(size_t)T_TOK * F_FF];   // 128 MB fp32 hidden scratch

// ---------------------------------------------------------------------------
// PTX helpers
// ---------------------------------------------------------------------------
__device__ __forceinline__ void cp_async16(uint32_t dst, const void* src) {
    asm volatile("cp.async.cg.shared.global [%0], [%1], 16;\n" :: "r"(dst), "l"(src));
}
__device__ __forceinline__ void cp_commit() {
    asm volatile("cp.async.commit_group;\n");
}
template <int N>
__device__ __forceinline__ void cp_wait() {
    asm volatile("cp.async.wait_group %0;\n" :: "n"(N));
}
__device__ __forceinline__ uint32_t f2tf32(float f) {
    uint32_t r;
    asm("cvt.rna.tf32.f32 %0, %1;" : "=r"(r) : "f"(f));
    return r;
}
__device__ __forceinline__ void mma_tf32(float* c, const uint32_t* a, const uint32_t* b) {
    asm volatile(
        "mma.sync.aligned.m16n8k8.row.col.f32.tf32.tf32.f32 "
        "{%0,%1,%2,%3}, {%4,%5,%6,%7}, {%8,%9}, {%0,%1,%2,%3};"
        : "+f"(c[0]), "+f"(c[1]), "+f"(c[2]), "+f"(c[3])
        : "r"(a[0]), "r"(a[1]), "r"(a[2]), "r"(a[3]), "r"(b[0]), "r"(b[1]));
}

// ---------------------------------------------------------------------------
// Kernel 0-3: routing pipeline (unchanged, known-good)
// ---------------------------------------------------------------------------
__global__ void init_kernel() {
    if (threadIdx.x < E_EXP) g_cnt[threadIdx.x] = 0;
}

__global__ void router_kernel(const float* __restrict__ x,
                              const float* __restrict__ Wr) {
    const int t   = blockIdx.x;
    const int tid = threadIdx.x;
    __shared__ float red[E_EXP][128];

    const float* xr = x + (size_t)t * D_MODEL;
    float acc[E_EXP];
#pragma unroll
    for (int e = 0; e < E_EXP; e++) acc[e] = 0.f;

    for (int d = tid; d < D_MODEL; d += 128) {
        float xv = xr[d];
#pragma unroll
        for (int e = 0; e < E_EXP; e++)
            acc[e] = fmaf(xv, Wr[(size_t)e * D_MODEL + d], acc[e]);
    }
#pragma unroll
    for (int e = 0; e < E_EXP; e++) red[e][tid] = acc[e];
    __syncthreads();

    for (int s = 64; s > 0; s >>= 1) {
        if (tid < s) {
#pragma unroll
            for (int e = 0; e < E_EXP; e++) red[e][tid] += red[e][tid + s];
        }
        __syncthreads();
    }

    if (tid == 0) {
        float m = red[0][0];
        int   bi = 0;
#pragma unroll
        for (int e = 1; e < E_EXP; e++) {
            float v = red[e][0];
            if (v > m) { m = v; bi = e; }   // strict > keeps first max (jnp.argmax)
        }
        float s = 0.f;
#pragma unroll
        for (int e = 0; e < E_EXP; e++) s += expf(red[e][0] - m);
        g_idx[t]  = bi;
        g_w[t]    = 1.0f / s;
        g_slot[t] = atomicAdd(&g_cnt[bi], 1);
    }
}

__global__ void offsets_kernel() {
    if (threadIdx.x == 0) {
        int s = 0;
        for (int e = 0; e < E_EXP; e++) { g_off[e] = s; s += g_cnt[e]; }
        g_off[E_EXP] = s;
    }
}

__global__ void perm_kernel() {
    int t = blockIdx.x * 256 + threadIdx.x;
    if (t < T_TOK) g_perm[g_off[g_idx[t]] + g_slot[t]] = t;
}

__device__ __forceinline__ float gelu_exact(float v) {
    return 0.5f * v * (1.0f + erff(v * 0.70710678118654752440f));
}

// ---------------------------------------------------------------------------
// Core mma.sync tf32 mainloop (shared by both GEMMs).
// Warp layout: warpM = warp&3 (32 rows), warpN = warp>>2 (64 cols).
// Per warp: 2 M-tiles (m16) x 8 N-tiles (n8), k-steps of 8.
// acc[mt][nt][4]: c0,c1 at (row=lane>>2, col=(lane&3)*2), c2,c3 at row+8.
// ---------------------------------------------------------------------------
struct Frag { float acc[2][8][4]; };

__device__ __forceinline__ void mma_tile_step(Frag& F, const float* As, const float* Bs,
                                              int warpM, int warpN, int lane) {
#pragma unroll
    for (int ks = 0; ks < BK / 8; ks++) {
        const float* Awp = As + (warpM * 32 + (lane >> 2)) * LDA_S + ks * 8 + (lane & 3);
        uint32_t ar[2][4];
#pragma unroll
        for (int mt = 0; mt < 2; mt++) {
            const float* ab = Awp + mt * 16 * LDA_S;
            ar[mt][0] = f2tf32(ab[0]);
            ar[mt][1] = f2tf32(ab[8 * LDA_S]);
            ar[mt][2] = f2tf32(ab[4]);
            ar[mt][3] = f2tf32(ab[8 * LDA_S + 4]);
        }
        const float* Bwp = Bs + (ks * 8 + (lane & 3)) * LDB_S + warpN * 64 + (lane >> 2);
        uint32_t br[8][2];
#pragma unroll
        for (int nt = 0; nt < 8; nt++) {
            br[nt][0] = f2tf32(Bwp[nt * 8]);
            br[nt][1] = f2tf32(Bwp[4 * LDB_S + nt * 8]);
        }
#pragma unroll
        for (int mt = 0; mt < 2; mt++)
#pragma unroll
            for (int nt = 0; nt < 8; nt++)
                mma_tf32(F.acc[mt][nt], ar[mt], br[nt]);
    }
}

// ---------------------------------------------------------------------------
// GEMM1: H[off+m, f] = gelu( sum_k X[perm[off+m], k] * W1[e][k][f] )
// ---------------------------------------------------------------------------
__global__ __launch_bounds__(NTH)
void gemm1_kernel(const float* __restrict__ x, const float* __restrict__ W1) {
    const int e = blockIdx.z, mt_blk = blockIdx.y, nt_blk = blockIdx.x;
    const int cnt = g_cnt[e], off = g_off[e];
    if (mt_blk * BM >= cnt) return;

    extern __shared__ float smem[];
    const int tid  = threadIdx.x;
    const int warp = tid >> 5, lane = tid & 31;
    const int warpM = warp & 3, warpN = warp >> 2;

    // A gather: row = tid>>1 (0..127), colseg = (tid&1)*16
    const int rA = tid >> 1;
    const int cA = (tid & 1) * 16;
    int growA = mt_blk * BM + rA;
    int rcA = growA < cnt ? growA : cnt - 1;
    const float* aSrc = x + (size_t)g_perm[off + rcA] * D_MODEL + cA;
    // B: row(k) = tid>>3 (0..31), colseg = (tid&7)*16
    const int rB = tid >> 3;
    const int cB = (tid & 7) * 16;
    const float* bSrc = W1 + (size_t)e * D_MODEL * F_FF
                           + (size_t)rB * F_FF + (size_t)nt_blk * BN + cB;

    uint32_t dA = (uint32_t)__cvta_generic_to_shared(&smem[rA * LDA_S + cA]);
    uint32_t dB = (uint32_t)__cvta_generic_to_shared(&smem[ABUF + rB * LDB_S + cB]);

    auto prefetch = [&](int b, int k0) {
        uint32_t add = (uint32_t)b * (uint32_t)(BUF_FLOATS * 4);
#pragma unroll
        for (int j = 0; j < 4; j++) cp_async16(dA + add + j * 16, aSrc + k0 + j * 4);
#pragma unroll
        for (int j = 0; j < 4; j++) cp_async16(dB + add + j * 16, bSrc + (size_t)k0 * F_FF + j * 4);
    };

    Frag F;
#pragma unroll
    for (int mt = 0; mt < 2; mt++)
#pragma unroll
        for (int nt = 0; nt < 8; nt++)
#pragma unroll
            for (int q = 0; q < 4; q++) F.acc[mt][nt][q] = 0.f;

    const int NKT = D_MODEL / BK;   // 64
    prefetch(0, 0);
    cp_commit();

#pragma unroll 1
    for (int kt = 0; kt < NKT; kt++) {
        const int cur = kt & 1;
        if (kt + 1 < NKT) {
            prefetch(cur ^ 1, (kt + 1) * BK);
            cp_commit();
            cp_wait<1>();
        } else {
            cp_wait<0>();
        }
        __syncthreads();
        const float* As = smem + cur * BUF_FLOATS;
        mma_tile_step(F, As, As + ABUF, warpM, warpN, lane);
        __syncthreads();
    }

    // Epilogue: GELU, direct float2 stores to compact H
    const int rbase = mt_blk * BM + warpM * 32 + (lane >> 2);
    const int cbase = nt_blk * BN + warpN * 64 + (lane & 3) * 2;
#pragma unroll
    for (int mt = 0; mt < 2; mt++) {
        int r0 = rbase + mt * 16;
#pragma unroll
        for (int h = 0; h < 2; h++) {
            int gr = r0 + h * 8;
            if (gr < cnt) {
                float* hb = g_H + (size_t)(off + gr) * F_FF;
#pragma unroll
                for (int nt = 0; nt < 8; nt++) {
                    float2 v;
                    v.x = gelu_exact(F.acc[mt][nt][h * 2 + 0]);
                    v.y = gelu_exact(F.acc[mt][nt][h * 2 + 1]);
                    *(float2*)(hb + cbase + nt * 8) = v;
                }
            }
        }
    }
}

// ---------------------------------------------------------------------------
// GEMM2: out[tok, d] = w[tok] * sum_f H[off+m, f] * W2[e][f][d]
// ---------------------------------------------------------------------------
__global__ __launch_bounds__(NTH)
void gemm2_kernel(const float* __restrict__ W2, float* __restrict__ out) {
    const int e = blockIdx.z, mt_blk = blockIdx.y, nt_blk = blockIdx.x;
    const int cnt = g_cnt[e], off = g_off[e];
    if (mt_blk * BM >= cnt) return;

    extern __shared__ float smem[];
    const int tid  = threadIdx.x;
    const int warp = tid >> 5, lane = tid & 31;
    const int warpM = warp & 3, warpN = warp >> 2;

    const int rA = tid >> 1;
    const int cA = (tid & 1) * 16;
    int growA = mt_blk * BM + rA;
    int rcA = growA < cnt ? growA : cnt - 1;
    const float* aSrc = g_H + (size_t)(off + rcA) * F_FF + cA;
    const int rB = tid >> 3;
    const int cB = (tid & 7) * 16;
    const float* bSrc = W2 + (size_t)e * F_FF * D_MODEL
                           + (size_t)rB * D_MODEL + (size_t)nt_blk * BN + cB;

    uint32_t dA = (uint32_t)__cvta_generic_to_shared(&smem[rA * LDA_S + cA]);
    uint32_t dB = (uint32_t)__cvta_generic_to_shared(&smem[ABUF + rB * LDB_S + cB]);

    auto prefetch = [&](int b, int k0) {
        uint32_t add = (uint32_t)b * (uint32_t)(BUF_FLOATS * 4);
#pragma unroll
        for (int j = 0; j < 4; j++) cp_async16(dA + add + j * 16, aSrc + k0 + j * 4);
#pragma unroll
        for (int j = 0; j < 4; j++) cp_async16(dB + add + j * 16, bSrc + (size_t)k0 * D_MODEL + j * 4);
    };

    Frag F;
#pragma unroll
    for (int mt = 0; mt < 2; mt++)
#pragma unroll
        for (int nt = 0; nt < 8; nt++)
#pragma unroll
            for (int q = 0; q < 4; q++) F.acc[mt][nt][q] = 0.f;

    const int NKT = F_FF / BK;   // 256
    prefetch(0, 0);
    cp_commit();

#pragma unroll 1
    for (int kt = 0; kt < NKT; kt++) {
        const int cur = kt & 1;
        if (kt + 1 < NKT) {
            prefetch(cur ^ 1, (kt + 1) * BK);
            cp_commit();
            cp_wait<1>();
        } else {
            cp_wait<0>();
        }
        __syncthreads();
        const float* As = smem + cur * BUF_FLOATS;
        mma_tile_step(F, As, As + ABUF, warpM, warpN, lane);
        __syncthreads();
    }

    // Epilogue: scale by router weight, scatter float2 to out[token]
    const int rbase = mt_blk * BM + warpM * 32 + (lane >> 2);
    const int cbase = nt_blk * BN + warpN * 64 + (lane & 3) * 2;
#pragma unroll
    for (int mt = 0; mt < 2; mt++) {
        int r0 = rbase + mt * 16;
#pragma unroll
        for (int h = 0; h < 2; h++) {
            int gr = r0 + h * 8;
            if (gr < cnt) {
                int tok = g_perm[off + gr];
                float wgt = g_w[tok];
                float* ob = out + (size_t)tok * D_MODEL;
#pragma unroll
                for (int nt = 0; nt < 8; nt++) {
                    float2 v;
                    v.x = F.acc[mt][nt][h * 2 + 0] * wgt;
                    v.y = F.acc[mt][nt][h * 2 + 1] * wgt;
                    *(float2*)(ob + cbase + nt * 8) = v;
                }
            }
        }
    }
}

// ---------------------------------------------------------------------------
// Launch
// ---------------------------------------------------------------------------
extern "C" void kernel_launch(void* const* d_in, const int* in_sizes, int n_in,
                              void* d_out, int out_size) {
    const float* x  = (const float*)d_in[0];   // [T, D]
    const float* Wr = (const float*)d_in[1];   // [E, D]
    const float* W1 = (const float*)d_in[2];   // [E, D, F]
    const float* W2 = (const float*)d_in[3];   // [E, F, D]
    float* out = (float*)d_out;                // [T, D]

    cudaFuncSetAttribute(gemm1_kernel,
                         cudaFuncAttributeMaxDynamicSharedMemorySize, SMEM_BYTES);
    cudaFuncSetAttribute(gemm2_kernel,
                         cudaFuncAttributeMaxDynamicSharedMemorySize, SMEM_BYTES);

    init_kernel<<<1, 32>>>();
    router_kernel<<<T_TOK, 128>>>(x, Wr);
    offsets_kernel<<<1, 32>>>();
    perm_kernel<<<T_TOK / 256, 256>>>();

    dim3 g1(F_FF / BN, T_TOK / BM, E_EXP);     // (64, 32, 8)
    gemm1_kernel<<<g1, NTH, SMEM_BYTES>>>(x, W1);

    dim3 g2(D_MODEL / BN, T_TOK / BM, E_EXP);  // (16, 32, 8)
    gemm2_kernel<<<g2, NTH, SMEM_BYTES>>>(W2, out);
}

// round 15
// speedup vs baseline: 1.7600x; 1.2046x over previous
#include <cuda_runtime.h>
#include <cuda_bf16.h>
#include <cstdint>

// Problem constants
#define T_TOK 4096
#define D_MODEL 2048
#define F_FF 8192
#define E_EXP 8

// GEMM tiling: 128x256 CTA tile, BK=32, 16 warps (4Mx4N), warp tile 32x64
#define BM 128
#define BN 256
#define BK 32
#define NTH 512
#define LDA_S 36                 // A smem stride (floats): bank=(4r+c)%32, conflict-free
#define LDB_S 264                // B smem stride (floats): 264%32=8, bank=(8k+n)%32, conflict-free
#define ABUF (BM * LDA_S)        // 4608 floats
#define BBUF (BK * LDB_S)        // 8448 floats
#define BUF_FLOATS (ABUF + BBUF) // 13056
#define SMEM_BYTES (2 * BUF_FLOATS * 4)   // 104448 B

// ---------------------------------------------------------------------------
// Device scratch
// ---------------------------------------------------------------------------
__device__ int   g_idx[T_TOK];
__device__ float g_w[T_TOK];
__device__ int   g_cnt[E_EXP];
__device__ int   g_off[E_EXP + 1];
__device__ int   g_slot[T_TOK];
__device__ int   g_perm[T_TOK];
__device__ float g_H[(size_t)T_TOK * F_FF];   // 128 MB fp32 hidden scratch

// ---------------------------------------------------------------------------
// PTX helpers
// ---------------------------------------------------------------------------
__device__ __forceinline__ void cp_async16(uint32_t dst, const void* src) {
    asm volatile("cp.async.cg.shared.global [%0], [%1], 16;\n" :: "r"(dst), "l"(src));
}
__device__ __forceinline__ void cp_commit() {
    asm volatile("cp.async.commit_group;\n");
}
template <int N>
__device__ __forceinline__ void cp_wait() {
    asm volatile("cp.async.wait_group %0;\n" :: "n"(N));
}
__device__ __forceinline__ uint32_t f2tf32(float f) {
    uint32_t r;
    asm("cvt.rna.tf32.f32 %0, %1;" : "=r"(r) : "f"(f));
    return r;
}
__device__ __forceinline__ void mma_tf32(float* c, const uint32_t* a, const uint32_t* b) {
    asm volatile(
        "mma.sync.aligned.m16n8k8.row.col.f32.tf32.tf32.f32 "
        "{%0,%1,%2,%3}, {%4,%5,%6,%7}, {%8,%9}, {%0,%1,%2,%3};"
        : "+f"(c[0]), "+f"(c[1]), "+f"(c[2]), "+f"(c[3])
        : "r"(a[0]), "r"(a[1]), "r"(a[2]), "r"(a[3]), "r"(b[0]), "r"(b[1]));
}

// ---------------------------------------------------------------------------
// Kernel 0-3: routing pipeline (unchanged, known-good)
// ---------------------------------------------------------------------------
__global__ void init_kernel() {
    if (threadIdx.x < E_EXP) g_cnt[threadIdx.x] = 0;
}

__global__ void router_kernel(const float* __restrict__ x,
                              const float* __restrict__ Wr) {
    const int t   = blockIdx.x;
    const int tid = threadIdx.x;
    __shared__ float red[E_EXP][128];

    const float* xr = x + (size_t)t * D_MODEL;
    float acc[E_EXP];
#pragma unroll
    for (int e = 0; e < E_EXP; e++) acc[e] = 0.f;

    for (int d = tid; d < D_MODEL; d += 128) {
        float xv = xr[d];
#pragma unroll
        for (int e = 0; e < E_EXP; e++)
            acc[e] = fmaf(xv, Wr[(size_t)e * D_MODEL + d], acc[e]);
    }
#pragma unroll
    for (int e = 0; e < E_EXP; e++) red[e][tid] = acc[e];
    __syncthreads();

    for (int s = 64; s > 0; s >>= 1) {
        if (tid < s) {
#pragma unroll
            for (int e = 0; e < E_EXP; e++) red[e][tid] += red[e][tid + s];
        }
        __syncthreads();
    }

    if (tid == 0) {
        float m = red[0][0];
        int   bi = 0;
#pragma unroll
        for (int e = 1; e < E_EXP; e++) {
            float v = red[e][0];
            if (v > m) { m = v; bi = e; }   // strict > keeps first max (jnp.argmax)
        }
        float s = 0.f;
#pragma unroll
        for (int e = 0; e < E_EXP; e++) s += expf(red[e][0] - m);
        g_idx[t]  = bi;
        g_w[t]    = 1.0f / s;
        g_slot[t] = atomicAdd(&g_cnt[bi], 1);
    }
}

__global__ void offsets_kernel() {
    if (threadIdx.x == 0) {
        int s = 0;
        for (int e = 0; e < E_EXP; e++) { g_off[e] = s; s += g_cnt[e]; }
        g_off[E_EXP] = s;
    }
}

__global__ void perm_kernel() {
    int t = blockIdx.x * 256 + threadIdx.x;
    if (t < T_TOK) g_perm[g_off[g_idx[t]] + g_slot[t]] = t;
}

__device__ __forceinline__ float gelu_exact(float v) {
    return 0.5f * v * (1.0f + erff(v * 0.70710678118654752440f));
}

// ---------------------------------------------------------------------------
// Core mma.sync tf32 mainloop (shared by both GEMMs).
// Warp layout: warpM = warp&3 (32 rows), warpN = warp>>2 (64 cols).
// Per warp: 2 M-tiles (m16) x 8 N-tiles (n8), k-steps of 8.
// ---------------------------------------------------------------------------
struct Frag { float acc[2][8][4]; };

__device__ __forceinline__ void mma_tile_step(Frag& F, const float* As, const float* Bs,
                                              int warpM, int warpN, int lane) {
#pragma unroll
    for (int ks = 0; ks < BK / 8; ks++) {
        const float* Awp = As + (warpM * 32 + (lane >> 2)) * LDA_S + ks * 8 + (lane & 3);
        uint32_t ar[2][4];
#pragma unroll
        for (int mt = 0; mt < 2; mt++) {
            const float* ab = Awp + mt * 16 * LDA_S;
            ar[mt][0] = f2tf32(ab[0]);
            ar[mt][1] = f2tf32(ab[8 * LDA_S]);
            ar[mt][2] = f2tf32(ab[4]);
            ar[mt][3] = f2tf32(ab[8 * LDA_S + 4]);
        }
        const float* Bwp = Bs + (ks * 8 + (lane & 3)) * LDB_S + warpN * 64 + (lane >> 2);
        uint32_t br[8][2];
#pragma unroll
        for (int nt = 0; nt < 8; nt++) {
            br[nt][0] = f2tf32(Bwp[nt * 8]);
            br[nt][1] = f2tf32(Bwp[4 * LDB_S + nt * 8]);
        }
#pragma unroll
        for (int mt = 0; mt < 2; mt++)
#pragma unroll
            for (int nt = 0; nt < 8; nt++)
                mma_tf32(F.acc[mt][nt], ar[mt], br[nt]);
    }
}

// ---------------------------------------------------------------------------
// GEMM1: H[off+m, f] = gelu( sum_k X[perm[off+m], k] * W1[e][k][f] )
// ---------------------------------------------------------------------------
__global__ __launch_bounds__(NTH)
void gemm1_kernel(const float* __restrict__ x, const float* __restrict__ W1) {
    const int e = blockIdx.z, mt_blk = blockIdx.y, nt_blk = blockIdx.x;
    const int cnt = g_cnt[e], off = g_off[e];
    if (mt_blk * BM >= cnt) return;

    extern __shared__ float smem[];
    const int tid  = threadIdx.x;
    const int warp = tid >> 5, lane = tid & 31;
    const int warpM = warp & 3, warpN = warp >> 2;

    // A gather: 1024 float4s, 2 per thread. row = tid>>2, colseg = (tid&3)*8
    const int rA = tid >> 2;
    const int cA = (tid & 3) * 8;
    int growA = mt_blk * BM + rA;
    int rcA = growA < cnt ? growA : cnt - 1;
    const float* aSrc = x + (size_t)g_perm[off + rcA] * D_MODEL + cA;
    // B: 2048 float4s, 4 per thread. rows k = tid>>4 (+16 for second pair)
    const int rB = tid >> 4;            // 0..31
    const int cB = (tid & 15) * 16;     // 0..240
    const float* bSrc = W1 + (size_t)e * D_MODEL * F_FF
                           + (size_t)rB * F_FF + (size_t)nt_blk * BN + cB;

    uint32_t dA = (uint32_t)__cvta_generic_to_shared(&smem[rA * LDA_S + cA]);
    uint32_t dB = (uint32_t)__cvta_generic_to_shared(&smem[ABUF + rB * LDB_S + cB]);

    auto prefetch = [&](int b, int k0) {
        uint32_t add = (uint32_t)b * (uint32_t)(BUF_FLOATS * 4);
#pragma unroll
        for (int j = 0; j < 2; j++) cp_async16(dA + add + j * 16, aSrc + k0 + j * 4);
#pragma unroll
        for (int j = 0; j < 4; j++) cp_async16(dB + add + j * 16, bSrc + (size_t)k0 * F_FF + j * 4);
    };

    Frag F;
#pragma unroll
    for (int mt = 0; mt < 2; mt++)
#pragma unroll
        for (int nt = 0; nt < 8; nt++)
#pragma unroll
            for (int q = 0; q < 4; q++) F.acc[mt][nt][q] = 0.f;

    const int NKT = D_MODEL / BK;   // 64
    prefetch(0, 0);
    cp_commit();

#pragma unroll 1
    for (int kt = 0; kt < NKT; kt++) {
        const int cur = kt & 1;
        if (kt + 1 < NKT) {
            prefetch(cur ^ 1, (kt + 1) * BK);
            cp_commit();
            cp_wait<1>();
        } else {
            cp_wait<0>();
        }
        __syncthreads();
        const float* As = smem + cur * BUF_FLOATS;
        mma_tile_step(F, As, As + ABUF, warpM, warpN, lane);
        __syncthreads();
    }

    // Epilogue: GELU, direct float2 stores to compact H
    const int rbase = mt_blk * BM + warpM * 32 + (lane >> 2);
    const int cbase = nt_blk * BN + warpN * 64 + (lane & 3) * 2;
#pragma unroll
    for (int mt = 0; mt < 2; mt++) {
        int r0 = rbase + mt * 16;
#pragma unroll
        for (int h = 0; h < 2; h++) {
            int gr = r0 + h * 8;
            if (gr < cnt) {
                float* hb = g_H + (size_t)(off + gr) * F_FF;
#pragma unroll
                for (int nt = 0; nt < 8; nt++) {
                    float2 v;
                    v.x = gelu_exact(F.acc[mt][nt][h * 2 + 0]);
                    v.y = gelu_exact(F.acc[mt][nt][h * 2 + 1]);
                    *(float2*)(hb + cbase + nt * 8) = v;
                }
            }
        }
    }
}

// ---------------------------------------------------------------------------
// GEMM2: out[tok, d] = w[tok] * sum_f H[off+m, f] * W2[e][f][d]
// ---------------------------------------------------------------------------
__global__ __launch_bounds__(NTH)
void gemm2_kernel(const float* __restrict__ W2, float* __restrict__ out) {
    const int e = blockIdx.z, mt_blk = blockIdx.y, nt_blk = blockIdx.x;
    const int cnt = g_cnt[e], off = g_off[e];
    if (mt_blk * BM >= cnt) return;

    extern __shared__ float smem[];
    const int tid  = threadIdx.x;
    const int warp = tid >> 5, lane = tid & 31;
    const int warpM = warp & 3, warpN = warp >> 2;

    const int rA = tid >> 2;
    const int cA = (tid & 3) * 8;
    int growA = mt_blk * BM + rA;
    int rcA = growA < cnt ? growA : cnt - 1;
    const float* aSrc = g_H + (size_t)(off + rcA) * F_FF + cA;
    const int rB = tid >> 4;
    const int cB = (tid & 15) * 16;
    const float* bSrc = W2 + (size_t)e * F_FF * D_MODEL
                           + (size_t)rB * D_MODEL + (size_t)nt_blk * BN + cB;

    uint32_t dA = (uint32_t)__cvta_generic_to_shared(&smem[rA * LDA_S + cA]);
    uint32_t dB = (uint32_t)__cvta_generic_to_shared(&smem[ABUF + rB * LDB_S + cB]);

    auto prefetch = [&](int b, int k0) {
        uint32_t add = (uint32_t)b * (uint32_t)(BUF_FLOATS * 4);
#pragma unroll
        for (int j = 0; j < 2; j++) cp_async16(dA + add + j * 16, aSrc + k0 + j * 4);
#pragma unroll
        for (int j = 0; j < 4; j++) cp_async16(dB + add + j * 16, bSrc + (size_t)k0 * D_MODEL + j * 4);
    };

    Frag F;
#pragma unroll
    for (int mt = 0; mt < 2; mt++)
#pragma unroll
        for (int nt = 0; nt < 8; nt++)
#pragma unroll
            for (int q = 0; q < 4; q++) F.acc[mt][nt][q] = 0.f;

    const int NKT = F_FF / BK;   // 256
    prefetch(0, 0);
    cp_commit();

#pragma unroll 1
    for (int kt = 0; kt < NKT; kt++) {
        const int cur = kt & 1;
        if (kt + 1 < NKT) {
            prefetch(cur ^ 1, (kt + 1) * BK);
            cp_commit();
            cp_wait<1>();
        } else {
            cp_wait<0>();
        }
        __syncthreads();
        const float* As = smem + cur * BUF_FLOATS;
        mma_tile_step(F, As, As + ABUF, warpM, warpN, lane);
        __syncthreads();
    }

    // Epilogue: scale by router weight, scatter float2 to out[token]
    const int rbase = mt_blk * BM + warpM * 32 + (lane >> 2);
    const int cbase = nt_blk * BN + warpN * 64 + (lane & 3) * 2;
#pragma unroll
    for (int mt = 0; mt < 2; mt++) {
        int r0 = rbase + mt * 16;
#pragma unroll
        for (int h = 0; h < 2; h++) {
            int gr = r0 + h * 8;
            if (gr < cnt) {
                int tok = g_perm[off + gr];
                float wgt = g_w[tok];
                float* ob = out + (size_t)tok * D_MODEL;
#pragma unroll
                for (int nt = 0; nt < 8; nt++) {
                    float2 v;
                    v.x = F.acc[mt][nt][h * 2 + 0] * wgt;
                    v.y = F.acc[mt][nt][h * 2 + 1] * wgt;
                    *(float2*)(ob + cbase + nt * 8) = v;
                }
            }
        }
    }
}

// ---------------------------------------------------------------------------
// Launch
// ---------------------------------------------------------------------------
extern "C" void kernel_launch(void* const* d_in, const int* in_sizes, int n_in,
                              void* d_out, int out_size) {
    const float* x  = (const float*)d_in[0];   // [T, D]
    const float* Wr = (const float*)d_in[1];   // [E, D]
    const float* W1 = (const float*)d_in[2];   // [E, D, F]
    const float* W2 = (const float*)d_in[3];   // [E, F, D]
    float* out = (float*)d_out;                // [T, D]

    cudaFuncSetAttribute(gemm1_kernel,
                         cudaFuncAttributeMaxDynamicSharedMemorySize, SMEM_BYTES);
    cudaFuncSetAttribute(gemm2_kernel,
                         cudaFuncAttributeMaxDynamicSharedMemorySize, SMEM_BYTES);

    init_kernel<<<1, 32>>>();
    router_kernel<<<T_TOK, 128>>>(x, Wr);
    offsets_kernel<<<1, 32>>>();
    perm_kernel<<<T_TOK / 256, 256>>>();

    dim3 g1(F_FF / BN, T_TOK / BM, E_EXP);     // (32, 32, 8)
    gemm1_kernel<<<g1, NTH, SMEM_BYTES>>>(x, W1);

    dim3 g2(D_MODEL / BN, T_TOK / BM, E_EXP);  // (8, 32, 8)
    gemm2_kernel<<<g2, NTH, SMEM_BYTES>>>(W2, out);
}